// round 16
// baseline (speedup 1.0000x reference)
#include <cuda_runtime.h>
#include <cuda_bf16.h>
#include <math.h>
#include <stdint.h>

#define Bsz 4
#define Tt 512
#define Cc 512
#define Hh 8
#define Dd 64
#define Ee 32
#define Ii 2048
#define Kk 2
#define Vv 32000
#define NTOK 2048
#define NPAIR 4096
#define MOE_YTILES 8

// ---------------- scratch ----------------
__device__ float g_h   [NTOK * Cc];
__device__ float g_x   [NTOK * Cc];
__device__ float g_q   [NTOK * Cc];
__device__ float g_k   [NTOK * Cc];
__device__ float g_v   [NTOK * Cc];
__device__ float g_ao  [NTOK * Cc];
__device__ float g_x2  [NTOK * Cc];
__device__ float g_rl  [NTOK * Ee];
__device__ float g_hid [NPAIR * Ii];
__device__ float g_po  [NPAIR * Cc];
__device__ int   g_sel [NPAIR];
__device__ float g_rw  [NPAIR];
__device__ int   g_cnt [Ee];
__device__ int   g_bucket[Ee * NPAIR];
__device__ float g_ht  [NTOK * Cc];    // h, tf32-rounded bits

// ---------------- mma helpers ----------------
__device__ __forceinline__ uint32_t smem_u32(const void* p) {
    uint32_t a;
    asm("{ .reg .u64 t; cvta.to.shared.u64 t, %1; cvt.u32.u64 %0, t; }" : "=r"(a) : "l"(p));
    return a;
}
__device__ __forceinline__ void cp16(uint32_t dst, const void* src) {
    asm volatile("cp.async.cg.shared.global [%0], [%1], 16;" :: "r"(dst), "l"(src));
}
__device__ __forceinline__ void f2tf2(float x, uint32_t& hi, uint32_t& lo) {
    uint32_t h;
    asm("cvt.rna.tf32.f32 %0, %1;" : "=r"(h) : "f"(x));
    float r = x - __uint_as_float(h);
    uint32_t l;
    asm("cvt.rna.tf32.f32 %0, %1;" : "=r"(l) : "f"(r));
    hi = h; lo = l;
}
__device__ __forceinline__ uint32_t f2tf(float f) {
    uint32_t u;
    asm("cvt.rna.tf32.f32 %0, %1;" : "=r"(u) : "f"(f));
    return u;
}
__device__ __forceinline__ void mma_tf32(float* d, const uint32_t* a, const uint32_t* b) {
    asm volatile(
        "mma.sync.aligned.m16n8k8.row.col.f32.tf32.tf32.f32 "
        "{%0,%1,%2,%3}, {%4,%5,%6,%7}, {%8,%9}, {%0,%1,%2,%3};"
        : "+f"(d[0]), "+f"(d[1]), "+f"(d[2]), "+f"(d[3])
        : "r"(a[0]), "r"(a[1]), "r"(a[2]), "r"(a[3]), "r"(b[0]), "r"(b[1]));
}

// ---------------- fused embedding + LN1 (+ counter zeroing) ----------------
__global__ void embed_ln_kernel(const int* __restrict__ ids, const float* __restrict__ emb,
                                const float* __restrict__ g, const float* __restrict__ b,
                                float* __restrict__ H, float* __restrict__ X) {
    int t = blockIdx.x, tid = threadIdx.x;
    if (t == 0 && tid < Ee) g_cnt[tid] = 0;
    int id = ids[t];
    const float* src = emb + (size_t)id * Cc;
    __shared__ float row[Cc];
    __shared__ float red[128];
    float s = 0.f;
    for (int c = tid; c < Cc; c += 128) {
        float v = src[c];
        row[c] = v;
        H[(size_t)t * Cc + c] = v;
        s += v;
    }
    red[tid] = s; __syncthreads();
    for (int k = 64; k > 0; k >>= 1) { if (tid < k) red[tid] += red[tid + k]; __syncthreads(); }
    float mu = red[0] / Cc; __syncthreads();
    float s2 = 0.f;
    for (int c = tid; c < Cc; c += 128) { float d = row[c] - mu; s2 += d * d; }
    red[tid] = s2; __syncthreads();
    for (int k = 64; k > 0; k >>= 1) { if (tid < k) red[tid] += red[tid + k]; __syncthreads(); }
    float inv = rsqrtf(red[0] / Cc + 1e-5f);
    for (int c = tid; c < Cc; c += 128)
        X[(size_t)t * Cc + c] = (row[c] - mu) * inv * g[c] + b[c];
}

// ---------------- fused LN2 + router + top-2 + bucket ----------------
__global__ void ln2_router_kernel(const float* __restrict__ Hin, const float* __restrict__ g,
                                  const float* __restrict__ b, const float* __restrict__ gate,
                                  float* __restrict__ X2, float* __restrict__ RL) {
    int t = blockIdx.x, tid = threadIdx.x;
    __shared__ float xr[Cc];
    __shared__ float red[128];
    __shared__ float part[4][32];
    const float* row = Hin + (size_t)t * Cc;
    float s = 0.f;
    for (int c = tid; c < Cc; c += 128) s += row[c];
    red[tid] = s; __syncthreads();
    for (int k = 64; k > 0; k >>= 1) { if (tid < k) red[tid] += red[tid + k]; __syncthreads(); }
    float mu = red[0] / Cc; __syncthreads();
    float s2 = 0.f;
    for (int c = tid; c < Cc; c += 128) { float d = row[c] - mu; s2 += d * d; }
    red[tid] = s2; __syncthreads();
    for (int k = 64; k > 0; k >>= 1) { if (tid < k) red[tid] += red[tid + k]; __syncthreads(); }
    float inv = rsqrtf(red[0] / Cc + 1e-5f);
    for (int c = tid; c < Cc; c += 128) {
        float v = (row[c] - mu) * inv * g[c] + b[c];
        xr[c] = v;
        X2[(size_t)t * Cc + c] = v;
    }
    __syncthreads();
    int e = tid & 31, chunk = tid >> 5;
    float p = 0.f;
    int c0 = chunk * 128;
    #pragma unroll 4
    for (int c = c0; c < c0 + 128; c++) p = fmaf(xr[c], gate[(size_t)c * Ee + e], p);
    part[chunk][e] = p;
    __syncthreads();
    if (tid < 32) {
        float lg = part[0][tid] + part[1][tid] + part[2][tid] + part[3][tid];
        RL[(size_t)t * Ee + tid] = lg;
        red[tid] = lg;
    }
    __syncthreads();
    if (tid == 0) {
        int i1 = 0; float v1 = red[0];
        for (int ee = 1; ee < Ee; ee++) if (red[ee] > v1) { v1 = red[ee]; i1 = ee; }
        int i2 = -1; float v2 = -3.4e38f;
        for (int ee = 0; ee < Ee; ee++) { if (ee == i1) continue; if (red[ee] > v2) { v2 = red[ee]; i2 = ee; } }
        float e2 = __expf(v2 - v1);
        float invs = 1.f / (1.f + e2);
        g_sel[t * 2] = i1; g_sel[t * 2 + 1] = i2;
        g_rw[t * 2] = invs; g_rw[t * 2 + 1] = e2 * invs;
        int s1 = atomicAdd(&g_cnt[i1], 1); g_bucket[i1 * NPAIR + s1] = t * 2;
        int s2 = atomicAdd(&g_cnt[i2], 1); g_bucket[i2 * NPAIR + s2] = t * 2 + 1;
    }
}

// ---------------- tf32(x3) tensor-core GEMM ----------------
// SWAP=1: blockIdx.x = rows, blockIdx.y = cols (B-strip L2 dedup).
// ACONV/BCONV=0: operand pre-rounded tf32 bits. STAGES: cp.async pipeline depth.
#define A_LD 36
#define B_LD 136
#define SMEM_A_ELEMS (128 * A_LD)
#define SMEM_B_ELEMS (32 * B_LD)
#define GEMM_SMEM_S(S) ((S) * (SMEM_A_ELEMS + SMEM_B_ELEMS) * 4)

template<int XTRA, int SWAP, int ACONV, int BCONV, int STAGES>
__global__ __launch_bounds__(256, 2)
void mma_gemm(const float* __restrict__ A,
              const float* __restrict__ B0, const float* __restrict__ B1,
              const float* __restrict__ B2,
              const float* __restrict__ R,
              float* __restrict__ C0, float* __restrict__ C1, float* __restrict__ C2,
              int M, int N, int K) {
    extern __shared__ float sm[];
    float* As = sm;
    float* Bs = sm + STAGES * SMEM_A_ELEMS;

    const float* B = (blockIdx.z == 0) ? B0 : ((blockIdx.z == 1) ? B1 : B2);
    float* C = (blockIdx.z == 0) ? C0 : ((blockIdx.z == 1) ? C1 : C2);

    int tid = threadIdx.x;
    int lane = tid & 31;
    int warp = tid >> 5;
    int wm = warp & 1;
    int wn = warp >> 1;
    int rowBase = (SWAP ? blockIdx.x : blockIdx.y) * 128;
    int colBase = (SWAP ? blockIdx.y : blockIdx.x) * 128;

    float acc[4][4][4];
    #pragma unroll
    for (int mi = 0; mi < 4; mi++)
        #pragma unroll
        for (int ni = 0; ni < 4; ni++)
            #pragma unroll
            for (int r = 0; r < 4; r++) acc[mi][ni][r] = 0.f;

    int nIter = K >> 5;

    auto loadTile = [&](int it, int buf) {
        int k0 = it * 32;
        float* Ab = As + buf * SMEM_A_ELEMS;
        float* Bb = Bs + buf * SMEM_B_ELEMS;
        #pragma unroll
        for (int t = 0; t < 4; t++) {
            int id = tid + t * 256;
            int ar = id >> 3, ac4 = id & 7;
            cp16(smem_u32(Ab + ar * A_LD + ac4 * 4),
                 A + (size_t)(rowBase + ar) * K + k0 + ac4 * 4);
            int br = id >> 5, bc4 = id & 31;
            cp16(smem_u32(Bb + br * B_LD + bc4 * 4),
                 B + (size_t)(k0 + br) * N + colBase + bc4 * 4);
        }
    };

    int rbase = wm * 64;
    int cbase = wn * 32;
    int lr = lane >> 2;
    int lc = lane & 3;

    auto computeTile = [&](const float* Ab, const float* Bb) {
        #pragma unroll
        for (int ks = 0; ks < 4; ks++) {
            int kk = ks * 8;
            uint32_t bh[4][2], bl[4][2];
            #pragma unroll
            for (int ni = 0; ni < 4; ni++) {
                const float* bp = Bb + (kk + lc) * B_LD + cbase + ni * 8 + lr;
                if (XTRA) {
                    f2tf2(bp[0], bh[ni][0], bl[ni][0]);
                    f2tf2(bp[4 * B_LD], bh[ni][1], bl[ni][1]);
                } else if (BCONV) {
                    bh[ni][0] = f2tf(bp[0]);
                    bh[ni][1] = f2tf(bp[4 * B_LD]);
                } else {
                    bh[ni][0] = __float_as_uint(bp[0]);
                    bh[ni][1] = __float_as_uint(bp[4 * B_LD]);
                }
            }
            #pragma unroll
            for (int mi = 0; mi < 4; mi++) {
                const float* ap = Ab + (rbase + mi * 16 + lr) * A_LD + kk + lc;
                uint32_t ah[4], al[4];
                if (XTRA) {
                    f2tf2(ap[0],            ah[0], al[0]);
                    f2tf2(ap[8 * A_LD],     ah[1], al[1]);
                    f2tf2(ap[4],            ah[2], al[2]);
                    f2tf2(ap[8 * A_LD + 4], ah[3], al[3]);
                } else if (ACONV) {
                    ah[0] = f2tf(ap[0]);
                    ah[1] = f2tf(ap[8 * A_LD]);
                    ah[2] = f2tf(ap[4]);
                    ah[3] = f2tf(ap[8 * A_LD + 4]);
                } else {
                    ah[0] = __float_as_uint(ap[0]);
                    ah[1] = __float_as_uint(ap[8 * A_LD]);
                    ah[2] = __float_as_uint(ap[4]);
                    ah[3] = __float_as_uint(ap[8 * A_LD + 4]);
                }
                #pragma unroll
                for (int ni = 0; ni < 4; ni++) {
                    mma_tf32(acc[mi][ni], ah, bh[ni]);
                    if (XTRA) {
                        mma_tf32(acc[mi][ni], al, bh[ni]);
                        mma_tf32(acc[mi][ni], ah, bl[ni]);
                    }
                }
            }
        }
    };

    if (STAGES == 2) {
        loadTile(0, 0);
        asm volatile("cp.async.commit_group;");
        for (int it = 0; it < nIter; it++) {
            int buf = it & 1;
            if (it + 1 < nIter) {
                loadTile(it + 1, buf ^ 1);
                asm volatile("cp.async.commit_group;");
                asm volatile("cp.async.wait_group 1;");
            } else {
                asm volatile("cp.async.wait_group 0;");
            }
            __syncthreads();
            computeTile(As + buf * SMEM_A_ELEMS, Bs + buf * SMEM_B_ELEMS);
            __syncthreads();
        }
    } else {
        // 3-stage: 2 tiles in flight hides an extra L2 round-trip
        loadTile(0, 0);
        asm volatile("cp.async.commit_group;");
        if (nIter > 1) {
            loadTile(1, 1);
            asm volatile("cp.async.commit_group;");
        }
        int buf = 0;
        for (int it = 0; it < nIter; it++) {
            if (it + 1 < nIter) asm volatile("cp.async.wait_group 1;");
            else                asm volatile("cp.async.wait_group 0;");
            __syncthreads();   // all warps done computing buf (it-1) -> safe to overwrite
            int nx = it + 2;
            if (nx < nIter) {
                int nbuf = buf + 2; if (nbuf >= 3) nbuf -= 3;
                loadTile(nx, nbuf);
                asm volatile("cp.async.commit_group;");
            }
            computeTile(As + buf * SMEM_A_ELEMS, Bs + buf * SMEM_B_ELEMS);
            buf++; if (buf == 3) buf = 0;
        }
    }

    #pragma unroll
    for (int mi = 0; mi < 4; mi++) {
        int gr0 = rowBase + rbase + mi * 16 + lr;
        #pragma unroll
        for (int ni = 0; ni < 4; ni++) {
            int gc = colBase + cbase + ni * 8 + 2 * lc;
            float2 v0 = make_float2(acc[mi][ni][0], acc[mi][ni][1]);
            float2 v1 = make_float2(acc[mi][ni][2], acc[mi][ni][3]);
            if (R) {
                const float2 r0 = *reinterpret_cast<const float2*>(R + (size_t)gr0 * N + gc);
                const float2 r1 = *reinterpret_cast<const float2*>(R + (size_t)(gr0 + 8) * N + gc);
                v0.x += r0.x; v0.y += r0.y; v1.x += r1.x; v1.y += r1.y;
            }
            *reinterpret_cast<float2*>(C + (size_t)gr0 * N + gc) = v0;
            *reinterpret_cast<float2*>(C + (size_t)(gr0 + 8) * N + gc) = v1;
        }
    }
}

// ---------------- MoE tensor-core GEMMs ----------------
#define MOE_M 64
#define MOE_A_ELEMS (MOE_M * A_LD)
#define MOE_B_ELEMS (32 * B_LD)
#define MOE_SMEM_BYTES ((2 * MOE_A_ELEMS + 2 * MOE_B_ELEMS) * 4 + 2 * MOE_M * 4)

__device__ __forceinline__ float gelu_f(float x) {
    return 0.5f * x * (1.f + erff(x * 0.70710678118654752f));
}

__global__ __launch_bounds__(256, 2)
void moe_mma(const float* __restrict__ Asrc, const float* __restrict__ W,
             float* __restrict__ FEO, int Kd, int Nd, int which) {
    int e = blockIdx.z;
    int n = g_cnt[e];
    int t0 = blockIdx.y * MOE_M;
    if (t0 >= n) return;
    int nt = min(MOE_M, n - t0);

    extern __shared__ float sm[];
    float* As = sm;
    float* Bs = sm + 2 * MOE_A_ELEMS;
    int* ps = (int*)(Bs + 2 * MOE_B_ELEMS);
    int* prow = ps + MOE_M;

    int tid = threadIdx.x;
    if (tid < MOE_M) {
        int p = (tid < nt) ? g_bucket[e * NPAIR + t0 + tid] : -1;
        ps[tid] = p;
        int r = (p >= 0) ? p : 0;
        prow[tid] = (which == 1) ? (r >> 1) : r;
    }
    __syncthreads();

    const float* Bw = W + (size_t)e * Cc * Ii + blockIdx.x * 128;

    int lane = tid & 31;
    int warp = tid >> 5;
    int wm = warp >> 1;
    int wn = warp & 1;
    int lr = lane >> 2;
    int lc = lane & 3;

    float acc[8][4];
    #pragma unroll
    for (int ni = 0; ni < 8; ni++)
        #pragma unroll
        for (int r = 0; r < 4; r++) acc[ni][r] = 0.f;

    int nIter = Kd >> 5;

    auto loadTile = [&](int it, int buf) {
        int k0 = it * 32;
        float* Ab = As + buf * MOE_A_ELEMS;
        float* Bb = Bs + buf * MOE_B_ELEMS;
        #pragma unroll
        for (int t = 0; t < 2; t++) {
            int id = tid + t * 256;
            int ar = id >> 3, ac4 = id & 7;
            cp16(smem_u32(Ab + ar * A_LD + ac4 * 4),
                 Asrc + (size_t)prow[ar] * Kd + k0 + ac4 * 4);
        }
        #pragma unroll
        for (int t = 0; t < 4; t++) {
            int id = tid + t * 256;
            int br = id >> 5, bc4 = id & 31;
            cp16(smem_u32(Bb + br * B_LD + bc4 * 4),
                 Bw + (size_t)(k0 + br) * Nd + bc4 * 4);
        }
    };

    loadTile(0, 0);
    asm volatile("cp.async.commit_group;");

    for (int it = 0; it < nIter; it++) {
        int buf = it & 1;
        if (it + 1 < nIter) {
            loadTile(it + 1, buf ^ 1);
            asm volatile("cp.async.commit_group;");
            asm volatile("cp.async.wait_group 1;");
        } else {
            asm volatile("cp.async.wait_group 0;");
        }
        __syncthreads();

        const float* Ab = As + buf * MOE_A_ELEMS;
        const float* Bb = Bs + buf * MOE_B_ELEMS;
        #pragma unroll
        for (int ks = 0; ks < 4; ks++) {
            int kk = ks * 8;
            const float* ap = Ab + (wm * 16 + lr) * A_LD + kk + lc;
            uint32_t ah[4];
            ah[0] = f2tf(ap[0]);
            ah[1] = f2tf(ap[8 * A_LD]);
            ah[2] = f2tf(ap[4]);
            ah[3] = f2tf(ap[8 * A_LD + 4]);
            #pragma unroll
            for (int ni = 0; ni < 8; ni++) {
                const float* bp = Bb + (kk + lc) * B_LD + wn * 64 + ni * 8 + lr;
                uint32_t bh[2];
                bh[0] = f2tf(bp[0]);
                bh[1] = f2tf(bp[4 * B_LD]);
                mma_tf32(acc[ni], ah, bh);
            }
        }
        __syncthreads();
    }

    int colBase = blockIdx.x * 128 + wn * 64;
    int tr0 = wm * 16 + lr;
    #pragma unroll
    for (int ni = 0; ni < 8; ni++) {
        int gc = colBase + ni * 8 + 2 * lc;
        if (tr0 < nt) {
            int p = ps[tr0];
            if (which == 1) {
                float* o = g_hid + (size_t)p * Ii + gc;
                o[0] = gelu_f(acc[ni][0]); o[1] = gelu_f(acc[ni][1]);
            } else {
                float* o = g_po + (size_t)p * Cc + gc;
                o[0] = acc[ni][0]; o[1] = acc[ni][1];
                if (FEO) {
                    float* f = FEO + ((size_t)(p >> 1) * Ee + e) * Cc + gc;
                    f[0] = acc[ni][0]; f[1] = acc[ni][1];
                }
            }
        }
        if (tr0 + 8 < nt) {
            int p = ps[tr0 + 8];
            if (which == 1) {
                float* o = g_hid + (size_t)p * Ii + gc;
                o[0] = gelu_f(acc[ni][2]); o[1] = gelu_f(acc[ni][3]);
            } else {
                float* o = g_po + (size_t)p * Cc + gc;
                o[0] = acc[ni][2]; o[1] = acc[ni][3];
                if (FEO) {
                    float* f = FEO + ((size_t)(p >> 1) * Ee + e) * Cc + gc;
                    f[0] = acc[ni][2]; f[1] = acc[ni][3];
                }
            }
        }
    }
}

// ---------------- flash-style tensor-core attention (now 2 CTAs/SM) ----------------
#define FA_LD 68
#define FA_SMEM (4 * 64 * FA_LD * 4)

__global__ __launch_bounds__(128, 2)
void fattn_kernel(const float* __restrict__ Q, const float* __restrict__ Km,
                  const float* __restrict__ Vm, float* __restrict__ AO) {
    extern __shared__ float fs[];
    float* Qs = fs;
    float* Ks = fs + 64 * FA_LD;
    float* Vs = fs + 2 * 64 * FA_LD;
    float* Ps = fs + 3 * 64 * FA_LD;

    int qt = blockIdx.x;
    int bh = blockIdx.y;
    int bb = bh >> 3, hh = bh & 7;
    int q0 = qt * 64;

    int tid = threadIdx.x;
    int lane = tid & 31;
    int warp = tid >> 5;
    int lr = lane >> 2;
    int lc = lane & 3;
    int rbase = warp * 16;

    #pragma unroll
    for (int t = 0; t < 8; t++) {
        int id = tid + t * 128;
        int r = id >> 4, c4 = id & 15;
        cp16(smem_u32(Qs + r * FA_LD + c4 * 4),
             Q + (size_t)(bb * Tt + q0 + r) * Cc + hh * Dd + c4 * 4);
    }
    asm volatile("cp.async.commit_group;");

    float m_a = -1e30f, m_b = -1e30f, l_a = 0.f, l_b = 0.f;
    float o[8][4];
    #pragma unroll
    for (int ni = 0; ni < 8; ni++)
        #pragma unroll
        for (int r = 0; r < 4; r++) o[ni][r] = 0.f;

    for (int jt = 0; jt <= qt; jt++) {
        int j0 = jt * 64;
        #pragma unroll
        for (int t = 0; t < 8; t++) {
            int id = tid + t * 128;
            int r = id >> 4, c4 = id & 15;
            cp16(smem_u32(Ks + r * FA_LD + c4 * 4),
                 Km + (size_t)(bb * Tt + j0 + r) * Cc + hh * Dd + c4 * 4);
        }
        asm volatile("cp.async.commit_group;");
        #pragma unroll
        for (int t = 0; t < 8; t++) {
            int id = tid + t * 128;
            int r = id >> 4, c4 = id & 15;
            float4 v = *reinterpret_cast<const float4*>(
                Vm + (size_t)(bb * Tt + j0 + r) * Cc + hh * Dd + c4 * 4);
            Vs[(c4 * 4 + 0) * FA_LD + r] = v.x;
            Vs[(c4 * 4 + 1) * FA_LD + r] = v.y;
            Vs[(c4 * 4 + 2) * FA_LD + r] = v.z;
            Vs[(c4 * 4 + 3) * FA_LD + r] = v.w;
        }
        asm volatile("cp.async.wait_group 0;");
        __syncthreads();

        float s[8][4];
        #pragma unroll
        for (int ni = 0; ni < 8; ni++)
            #pragma unroll
            for (int r = 0; r < 4; r++) s[ni][r] = 0.f;

        #pragma unroll
        for (int ks = 0; ks < 8; ks++) {
            int kk = ks * 8;
            const float* ap = Qs + (rbase + lr) * FA_LD + kk + lc;
            uint32_t ah[4], al[4];
            f2tf2(ap[0],              ah[0], al[0]);
            f2tf2(ap[8 * FA_LD],      ah[1], al[1]);
            f2tf2(ap[4],              ah[2], al[2]);
            f2tf2(ap[8 * FA_LD + 4],  ah[3], al[3]);
            #pragma unroll
            for (int ni = 0; ni < 8; ni++) {
                const float* bp = Ks + (ni * 8 + lr) * FA_LD + kk + lc;
                uint32_t bhh[2], bll[2];
                f2tf2(bp[0], bhh[0], bll[0]);
                f2tf2(bp[4], bhh[1], bll[1]);
                mma_tf32(s[ni], ah, bhh);
                mma_tf32(s[ni], al, bhh);
                mma_tf32(s[ni], ah, bll);
            }
        }

        int qga = q0 + rbase + lr;
        int qgb = qga + 8;
        #pragma unroll
        for (int ni = 0; ni < 8; ni++) {
            int c0 = j0 + ni * 8 + 2 * lc;
            int c1 = c0 + 1;
            s[ni][0] = (c0 <= qga) ? s[ni][0] * 0.125f : -1e30f;
            s[ni][1] = (c1 <= qga) ? s[ni][1] * 0.125f : -1e30f;
            s[ni][2] = (c0 <= qgb) ? s[ni][2] * 0.125f : -1e30f;
            s[ni][3] = (c1 <= qgb) ? s[ni][3] * 0.125f : -1e30f;
        }

        float mxa = -1e30f, mxb = -1e30f;
        #pragma unroll
        for (int ni = 0; ni < 8; ni++) {
            mxa = fmaxf(mxa, fmaxf(s[ni][0], s[ni][1]));
            mxb = fmaxf(mxb, fmaxf(s[ni][2], s[ni][3]));
        }
        mxa = fmaxf(mxa, __shfl_xor_sync(0xffffffff, mxa, 1));
        mxa = fmaxf(mxa, __shfl_xor_sync(0xffffffff, mxa, 2));
        mxb = fmaxf(mxb, __shfl_xor_sync(0xffffffff, mxb, 1));
        mxb = fmaxf(mxb, __shfl_xor_sync(0xffffffff, mxb, 2));

        float mna = fmaxf(m_a, mxa);
        float mnb = fmaxf(m_b, mxb);
        float sca = __expf(m_a - mna);
        float scb = __expf(m_b - mnb);

        float sa = 0.f, sb = 0.f;
        #pragma unroll
        for (int ni = 0; ni < 8; ni++) {
            float p0 = __expf(s[ni][0] - mna);
            float p1 = __expf(s[ni][1] - mna);
            float p2 = __expf(s[ni][2] - mnb);
            float p3 = __expf(s[ni][3] - mnb);
            sa += p0 + p1; sb += p2 + p3;
            int cc0 = ni * 8 + 2 * lc;
            Ps[(rbase + lr) * FA_LD + cc0]     = p0;
            Ps[(rbase + lr) * FA_LD + cc0 + 1] = p1;
            Ps[(rbase + lr + 8) * FA_LD + cc0]     = p2;
            Ps[(rbase + lr + 8) * FA_LD + cc0 + 1] = p3;
        }
        sa += __shfl_xor_sync(0xffffffff, sa, 1);
        sa += __shfl_xor_sync(0xffffffff, sa, 2);
        sb += __shfl_xor_sync(0xffffffff, sb, 1);
        sb += __shfl_xor_sync(0xffffffff, sb, 2);

        l_a = l_a * sca + sa;
        l_b = l_b * scb + sb;
        m_a = mna; m_b = mnb;

        #pragma unroll
        for (int ni = 0; ni < 8; ni++) {
            o[ni][0] *= sca; o[ni][1] *= sca;
            o[ni][2] *= scb; o[ni][3] *= scb;
        }
        __syncwarp();

        #pragma unroll
        for (int ks = 0; ks < 8; ks++) {
            int kk = ks * 8;
            const float* ap = Ps + (rbase + lr) * FA_LD + kk + lc;
            uint32_t ah[4], al[4];
            f2tf2(ap[0],              ah[0], al[0]);
            f2tf2(ap[8 * FA_LD],      ah[1], al[1]);
            f2tf2(ap[4],              ah[2], al[2]);
            f2tf2(ap[8 * FA_LD + 4],  ah[3], al[3]);
            #pragma unroll
            for (int ni = 0; ni < 8; ni++) {
                const float* bp = Vs + (ni * 8 + lr) * FA_LD + kk + lc;
                uint32_t bhh[2], bll[2];
                f2tf2(bp[0], bhh[0], bll[0]);
                f2tf2(bp[4], bhh[1], bll[1]);
                mma_tf32(o[ni], ah, bhh);
                mma_tf32(o[ni], al, bhh);
                mma_tf32(o[ni], ah, bll);
            }
        }
        __syncthreads();
    }

    float ia = 1.f / l_a;
    float ib = 1.f / l_b;
    int qra = bb * Tt + q0 + rbase + lr;
    #pragma unroll
    for (int ni = 0; ni < 8; ni++) {
        int gc = hh * Dd + ni * 8 + 2 * lc;
        *reinterpret_cast<float2*>(AO + (size_t)qra * Cc + gc) =
            make_float2(o[ni][0] * ia, o[ni][1] * ia);
        *reinterpret_cast<float2*>(AO + (size_t)(qra + 8) * Cc + gc) =
            make_float2(o[ni][2] * ib, o[ni][3] * ib);
    }
}

// ---------------- combine + h tf32 round (fused) ----------------
__global__ void moe_combine_round(float* __restrict__ HT) {
    int t = blockIdx.x;
    float w0 = g_rw[t * 2], w1r = g_rw[t * 2 + 1];
    float* hrow = g_h + (size_t)t * Cc;
    const float* p0 = g_po + (size_t)(t * 2) * Cc;
    const float* p1 = g_po + (size_t)(t * 2 + 1) * Cc;
    for (int c = threadIdx.x; c < Cc; c += 128) {
        float nv = hrow[c] + w0 * p0[c] + w1r * p1[c];
        hrow[c] = nv;
        HT[(size_t)t * Cc + c] = __uint_as_float(f2tf(nv));
    }
}

// ---------------- launch ----------------
extern "C" void kernel_launch(void* const* d_in, const int* in_sizes, int n_in,
                              void* d_out, int out_size) {
    const int*   ids  = (const int*)d_in[0];
    const float* emb  = (const float*)d_in[1];
    const float* wq   = (const float*)d_in[2];
    const float* wk   = (const float*)d_in[3];
    const float* wv   = (const float*)d_in[4];
    const float* wo   = (const float*)d_in[5];
    const float* gate = (const float*)d_in[6];
    const float* w1   = (const float*)d_in[7];
    const float* w2   = (const float*)d_in[8];
    const float* g1   = (const float*)d_in[9];
    const float* b1   = (const float*)d_in[10];
    const float* g2   = (const float*)d_in[11];
    const float* b2   = (const float*)d_in[12];
    const float* lm   = (const float*)d_in[13];
    float* out = (float*)d_out;

    float *p_h, *p_x, *p_q, *p_k, *p_v, *p_ao, *p_x2, *p_rl, *p_hid, *p_ht;
    cudaGetSymbolAddress((void**)&p_h,  g_h);
    cudaGetSymbolAddress((void**)&p_x,  g_x);
    cudaGetSymbolAddress((void**)&p_q,  g_q);
    cudaGetSymbolAddress((void**)&p_k,  g_k);
    cudaGetSymbolAddress((void**)&p_v,  g_v);
    cudaGetSymbolAddress((void**)&p_ao, g_ao);
    cudaGetSymbolAddress((void**)&p_x2, g_x2);
    cudaGetSymbolAddress((void**)&p_rl, g_rl);
    cudaGetSymbolAddress((void**)&p_hid, g_hid);
    cudaGetSymbolAddress((void**)&p_ht, g_ht);

    cudaFuncSetAttribute((const void*)mma_gemm<1,0,1,1,2>,
                         cudaFuncAttributeMaxDynamicSharedMemorySize, GEMM_SMEM_S(2));
    cudaFuncSetAttribute((const void*)mma_gemm<0,1,0,1,3>,
                         cudaFuncAttributeMaxDynamicSharedMemorySize, GEMM_SMEM_S(3));
    cudaFuncSetAttribute((const void*)moe_mma,
                         cudaFuncAttributeMaxDynamicSharedMemorySize, MOE_SMEM_BYTES);
    cudaFuncSetAttribute((const void*)fattn_kernel,
                         cudaFuncAttributeMaxDynamicSharedMemorySize, FA_SMEM);

    const size_t L_LOG = (size_t)NTOK * Vv;
    const size_t L_FEO = (size_t)NTOK * Ee * Cc;
    const size_t L_RL  = (size_t)NTOK * Ee;
    const size_t L_X2  = (size_t)NTOK * Cc;
    const size_t OFF_FEO = L_LOG;
    const size_t OFF_RL  = OFF_FEO + L_FEO;
    const size_t OFF_X2  = OFF_RL + L_RL;
    bool full = (size_t)out_size >= OFF_X2 + L_X2;

    // fused embedding + LN1 (+ counter zeroing)
    embed_ln_kernel<<<NTOK, 128>>>(ids, emb, g1, b1, p_h, p_x);

    // fused QKV (2-stage, proven)
    mma_gemm<1,0,1,1,2><<<dim3(Cc / 128, NTOK / 128, 3), 256, GEMM_SMEM_S(2)>>>(
        p_x, wq, wk, wv, nullptr, p_q, p_k, p_v, NTOK, Cc, Cc);

    fattn_kernel<<<dim3(Tt / 64, Bsz * Hh), 128, FA_SMEM>>>(p_q, p_k, p_v, p_ao);

    mma_gemm<1,0,1,1,2><<<dim3(Cc / 128, NTOK / 128, 1), 256, GEMM_SMEM_S(2)>>>(
        p_ao, wo, wo, wo, p_h, p_h, p_h, p_h, NTOK, Cc, Cc);

    // fused LN2 + router + top-2 + bucketing
    ln2_router_kernel<<<NTOK, 128>>>(p_h, g2, b2, gate, p_x2, p_rl);

    if (full) cudaMemsetAsync(out + OFF_FEO, 0, L_FEO * sizeof(float));

    moe_mma<<<dim3(Ii / 128, MOE_YTILES, Ee), 256, MOE_SMEM_BYTES>>>(
        p_x2, w1, nullptr, Cc, Ii, 1);
    moe_mma<<<dim3(Cc / 128, MOE_YTILES, Ee), 256, MOE_SMEM_BYTES>>>(
        p_hid, w2, full ? (out + OFF_FEO) : nullptr, Ii, Cc, 2);

    moe_combine_round<<<NTOK, 128>>>(p_ht);

    // lm_head: 3-stage pipeline, A pre-rounded, B in-loop CVT
    mma_gemm<0,1,0,1,3><<<dim3(NTOK / 128, Vv / 128, 1), 256, GEMM_SMEM_S(3)>>>(
        p_ht, lm, lm, lm, nullptr, out, out, out, NTOK, Vv, Cc);

    if (full) {
        cudaMemcpyAsync(out + OFF_RL, p_rl, L_RL * sizeof(float), cudaMemcpyDeviceToDevice);
        cudaMemcpyAsync(out + OFF_X2, p_x2, L_X2 * sizeof(float), cudaMemcpyDeviceToDevice);
    }
}

// round 17
// speedup vs baseline: 1.0025x; 1.0025x over previous
#include <cuda_runtime.h>
#include <cuda_bf16.h>
#include <math.h>
#include <stdint.h>

#define Bsz 4
#define Tt 512
#define Cc 512
#define Hh 8
#define Dd 64
#define Ee 32
#define Ii 2048
#define Kk 2
#define Vv 32000
#define NTOK 2048
#define NPAIR 4096
#define MOE_YTILES 8

// ---------------- scratch ----------------
__device__ float g_h   [NTOK * Cc];
__device__ float g_x   [NTOK * Cc];
__device__ float g_q   [NTOK * Cc];
__device__ float g_k   [NTOK * Cc];
__device__ float g_v   [NTOK * Cc];
__device__ float g_ao  [NTOK * Cc];
__device__ float g_x2  [NTOK * Cc];
__device__ float g_rl  [NTOK * Ee];
__device__ float g_hid [NPAIR * Ii];
__device__ float g_po  [NPAIR * Cc];
__device__ int   g_sel [NPAIR];
__device__ float g_rw  [NPAIR];
__device__ int   g_cnt [Ee];
__device__ int   g_bucket[Ee * NPAIR];
__device__ float g_ht  [NTOK * Cc];    // h, tf32-rounded bits

// ---------------- mma helpers ----------------
__device__ __forceinline__ uint32_t smem_u32(const void* p) {
    uint32_t a;
    asm("{ .reg .u64 t; cvta.to.shared.u64 t, %1; cvt.u32.u64 %0, t; }" : "=r"(a) : "l"(p));
    return a;
}
__device__ __forceinline__ void cp16(uint32_t dst, const void* src) {
    asm volatile("cp.async.cg.shared.global [%0], [%1], 16;" :: "r"(dst), "l"(src));
}
__device__ __forceinline__ void f2tf2(float x, uint32_t& hi, uint32_t& lo) {
    uint32_t h;
    asm("cvt.rna.tf32.f32 %0, %1;" : "=r"(h) : "f"(x));
    float r = x - __uint_as_float(h);
    uint32_t l;
    asm("cvt.rna.tf32.f32 %0, %1;" : "=r"(l) : "f"(r));
    hi = h; lo = l;
}
__device__ __forceinline__ uint32_t f2tf(float f) {
    uint32_t u;
    asm("cvt.rna.tf32.f32 %0, %1;" : "=r"(u) : "f"(f));
    return u;
}
__device__ __forceinline__ void mma_tf32(float* d, const uint32_t* a, const uint32_t* b) {
    asm volatile(
        "mma.sync.aligned.m16n8k8.row.col.f32.tf32.tf32.f32 "
        "{%0,%1,%2,%3}, {%4,%5,%6,%7}, {%8,%9}, {%0,%1,%2,%3};"
        : "+f"(d[0]), "+f"(d[1]), "+f"(d[2]), "+f"(d[3])
        : "r"(a[0]), "r"(a[1]), "r"(a[2]), "r"(a[3]), "r"(b[0]), "r"(b[1]));
}

// ---------------- fused embedding + LN1 (+ counter zeroing) ----------------
__global__ void embed_ln_kernel(const int* __restrict__ ids, const float* __restrict__ emb,
                                const float* __restrict__ g, const float* __restrict__ b,
                                float* __restrict__ H, float* __restrict__ X) {
    int t = blockIdx.x, tid = threadIdx.x;
    if (t == 0 && tid < Ee) g_cnt[tid] = 0;
    int id = ids[t];
    const float* src = emb + (size_t)id * Cc;
    __shared__ float row[Cc];
    __shared__ float red[128];
    float s = 0.f;
    for (int c = tid; c < Cc; c += 128) {
        float v = src[c];
        row[c] = v;
        H[(size_t)t * Cc + c] = v;
        s += v;
    }
    red[tid] = s; __syncthreads();
    for (int k = 64; k > 0; k >>= 1) { if (tid < k) red[tid] += red[tid + k]; __syncthreads(); }
    float mu = red[0] / Cc; __syncthreads();
    float s2 = 0.f;
    for (int c = tid; c < Cc; c += 128) { float d = row[c] - mu; s2 += d * d; }
    red[tid] = s2; __syncthreads();
    for (int k = 64; k > 0; k >>= 1) { if (tid < k) red[tid] += red[tid + k]; __syncthreads(); }
    float inv = rsqrtf(red[0] / Cc + 1e-5f);
    for (int c = tid; c < Cc; c += 128)
        X[(size_t)t * Cc + c] = (row[c] - mu) * inv * g[c] + b[c];
}

// ---------------- fused LN2 + router + top-2 + bucket ----------------
__global__ void ln2_router_kernel(const float* __restrict__ Hin, const float* __restrict__ g,
                                  const float* __restrict__ b, const float* __restrict__ gate,
                                  float* __restrict__ X2, float* __restrict__ RL) {
    int t = blockIdx.x, tid = threadIdx.x;
    __shared__ float xr[Cc];
    __shared__ float red[128];
    __shared__ float part[4][32];
    const float* row = Hin + (size_t)t * Cc;
    float s = 0.f;
    for (int c = tid; c < Cc; c += 128) s += row[c];
    red[tid] = s; __syncthreads();
    for (int k = 64; k > 0; k >>= 1) { if (tid < k) red[tid] += red[tid + k]; __syncthreads(); }
    float mu = red[0] / Cc; __syncthreads();
    float s2 = 0.f;
    for (int c = tid; c < Cc; c += 128) { float d = row[c] - mu; s2 += d * d; }
    red[tid] = s2; __syncthreads();
    for (int k = 64; k > 0; k >>= 1) { if (tid < k) red[tid] += red[tid + k]; __syncthreads(); }
    float inv = rsqrtf(red[0] / Cc + 1e-5f);
    for (int c = tid; c < Cc; c += 128) {
        float v = (row[c] - mu) * inv * g[c] + b[c];
        xr[c] = v;
        X2[(size_t)t * Cc + c] = v;
    }
    __syncthreads();
    int e = tid & 31, chunk = tid >> 5;
    float p = 0.f;
    int c0 = chunk * 128;
    #pragma unroll 4
    for (int c = c0; c < c0 + 128; c++) p = fmaf(xr[c], gate[(size_t)c * Ee + e], p);
    part[chunk][e] = p;
    __syncthreads();
    if (tid < 32) {
        float lg = part[0][tid] + part[1][tid] + part[2][tid] + part[3][tid];
        RL[(size_t)t * Ee + tid] = lg;
        red[tid] = lg;
    }
    __syncthreads();
    if (tid == 0) {
        int i1 = 0; float v1 = red[0];
        for (int ee = 1; ee < Ee; ee++) if (red[ee] > v1) { v1 = red[ee]; i1 = ee; }
        int i2 = -1; float v2 = -3.4e38f;
        for (int ee = 0; ee < Ee; ee++) { if (ee == i1) continue; if (red[ee] > v2) { v2 = red[ee]; i2 = ee; } }
        float e2 = __expf(v2 - v1);
        float invs = 1.f / (1.f + e2);
        g_sel[t * 2] = i1; g_sel[t * 2 + 1] = i2;
        g_rw[t * 2] = invs; g_rw[t * 2 + 1] = e2 * invs;
        int s1 = atomicAdd(&g_cnt[i1], 1); g_bucket[i1 * NPAIR + s1] = t * 2;
        int s2 = atomicAdd(&g_cnt[i2], 1); g_bucket[i2 * NPAIR + s2] = t * 2 + 1;
    }
}

// ---------------- tf32(x3) tensor-core GEMM (proven 2-stage schedule) ----------------
// SWAP=1: blockIdx.x = rows, blockIdx.y = cols (B-strip L2 dedup).
// ACONV/BCONV=0: operand pre-rounded tf32 bits; skip in-loop cvt.
#define A_LD 36
#define B_LD 136
#define SMEM_A_ELEMS (128 * A_LD)
#define SMEM_B_ELEMS (32 * B_LD)
#define GEMM_SMEM_BYTES ((2 * SMEM_A_ELEMS + 2 * SMEM_B_ELEMS) * 4)

template<int XTRA, int SWAP, int ACONV, int BCONV>
__global__ __launch_bounds__(256, 2)
void mma_gemm(const float* __restrict__ A,
              const float* __restrict__ B0, const float* __restrict__ B1,
              const float* __restrict__ B2,
              const float* __restrict__ R,
              float* __restrict__ C0, float* __restrict__ C1, float* __restrict__ C2,
              int M, int N, int K) {
    extern __shared__ float sm[];
    float* As = sm;
    float* Bs = sm + 2 * SMEM_A_ELEMS;

    const float* B = (blockIdx.z == 0) ? B0 : ((blockIdx.z == 1) ? B1 : B2);
    float* C = (blockIdx.z == 0) ? C0 : ((blockIdx.z == 1) ? C1 : C2);

    int tid = threadIdx.x;
    int lane = tid & 31;
    int warp = tid >> 5;
    int wm = warp & 1;
    int wn = warp >> 1;
    int rowBase = (SWAP ? blockIdx.x : blockIdx.y) * 128;
    int colBase = (SWAP ? blockIdx.y : blockIdx.x) * 128;

    float acc[4][4][4];
    #pragma unroll
    for (int mi = 0; mi < 4; mi++)
        #pragma unroll
        for (int ni = 0; ni < 4; ni++)
            #pragma unroll
            for (int r = 0; r < 4; r++) acc[mi][ni][r] = 0.f;

    int nIter = K >> 5;

    auto loadTile = [&](int it, int buf) {
        int k0 = it * 32;
        float* Ab = As + buf * SMEM_A_ELEMS;
        float* Bb = Bs + buf * SMEM_B_ELEMS;
        #pragma unroll
        for (int t = 0; t < 4; t++) {
            int id = tid + t * 256;
            int ar = id >> 3, ac4 = id & 7;
            cp16(smem_u32(Ab + ar * A_LD + ac4 * 4),
                 A + (size_t)(rowBase + ar) * K + k0 + ac4 * 4);
            int br = id >> 5, bc4 = id & 31;
            cp16(smem_u32(Bb + br * B_LD + bc4 * 4),
                 B + (size_t)(k0 + br) * N + colBase + bc4 * 4);
        }
    };

    loadTile(0, 0);
    asm volatile("cp.async.commit_group;");

    int rbase = wm * 64;
    int cbase = wn * 32;
    int lr = lane >> 2;
    int lc = lane & 3;

    for (int it = 0; it < nIter; it++) {
        int buf = it & 1;
        if (it + 1 < nIter) {
            loadTile(it + 1, buf ^ 1);
            asm volatile("cp.async.commit_group;");
            asm volatile("cp.async.wait_group 1;");
        } else {
            asm volatile("cp.async.wait_group 0;");
        }
        __syncthreads();

        const float* Ab = As + buf * SMEM_A_ELEMS;
        const float* Bb = Bs + buf * SMEM_B_ELEMS;
        #pragma unroll
        for (int ks = 0; ks < 4; ks++) {
            int kk = ks * 8;
            uint32_t bh[4][2], bl[4][2];
            #pragma unroll
            for (int ni = 0; ni < 4; ni++) {
                const float* bp = Bb + (kk + lc) * B_LD + cbase + ni * 8 + lr;
                if (XTRA) {
                    f2tf2(bp[0], bh[ni][0], bl[ni][0]);
                    f2tf2(bp[4 * B_LD], bh[ni][1], bl[ni][1]);
                } else if (BCONV) {
                    bh[ni][0] = f2tf(bp[0]);
                    bh[ni][1] = f2tf(bp[4 * B_LD]);
                } else {
                    bh[ni][0] = __float_as_uint(bp[0]);
                    bh[ni][1] = __float_as_uint(bp[4 * B_LD]);
                }
            }
            #pragma unroll
            for (int mi = 0; mi < 4; mi++) {
                const float* ap = Ab + (rbase + mi * 16 + lr) * A_LD + kk + lc;
                uint32_t ah[4], al[4];
                if (XTRA) {
                    f2tf2(ap[0],            ah[0], al[0]);
                    f2tf2(ap[8 * A_LD],     ah[1], al[1]);
                    f2tf2(ap[4],            ah[2], al[2]);
                    f2tf2(ap[8 * A_LD + 4], ah[3], al[3]);
                } else if (ACONV) {
                    ah[0] = f2tf(ap[0]);
                    ah[1] = f2tf(ap[8 * A_LD]);
                    ah[2] = f2tf(ap[4]);
                    ah[3] = f2tf(ap[8 * A_LD + 4]);
                } else {
                    ah[0] = __float_as_uint(ap[0]);
                    ah[1] = __float_as_uint(ap[8 * A_LD]);
                    ah[2] = __float_as_uint(ap[4]);
                    ah[3] = __float_as_uint(ap[8 * A_LD + 4]);
                }
                #pragma unroll
                for (int ni = 0; ni < 4; ni++) {
                    mma_tf32(acc[mi][ni], ah, bh[ni]);
                    if (XTRA) {
                        mma_tf32(acc[mi][ni], al, bh[ni]);
                        mma_tf32(acc[mi][ni], ah, bl[ni]);
                    }
                }
            }
        }
        __syncthreads();
    }

    #pragma unroll
    for (int mi = 0; mi < 4; mi++) {
        int gr0 = rowBase + rbase + mi * 16 + lr;
        #pragma unroll
        for (int ni = 0; ni < 4; ni++) {
            int gc = colBase + cbase + ni * 8 + 2 * lc;
            float2 v0 = make_float2(acc[mi][ni][0], acc[mi][ni][1]);
            float2 v1 = make_float2(acc[mi][ni][2], acc[mi][ni][3]);
            if (R) {
                const float2 r0 = *reinterpret_cast<const float2*>(R + (size_t)gr0 * N + gc);
                const float2 r1 = *reinterpret_cast<const float2*>(R + (size_t)(gr0 + 8) * N + gc);
                v0.x += r0.x; v0.y += r0.y; v1.x += r1.x; v1.y += r1.y;
            }
            *reinterpret_cast<float2*>(C + (size_t)gr0 * N + gc) = v0;
            *reinterpret_cast<float2*>(C + (size_t)(gr0 + 8) * N + gc) = v1;
        }
    }
}

// ---------------- MoE tensor-core GEMMs ----------------
#define MOE_M 64
#define MOE_A_ELEMS (MOE_M * A_LD)
#define MOE_B_ELEMS (32 * B_LD)
#define MOE_SMEM_BYTES ((2 * MOE_A_ELEMS + 2 * MOE_B_ELEMS) * 4 + 2 * MOE_M * 4)

__device__ __forceinline__ float gelu_f(float x) {
    return 0.5f * x * (1.f + erff(x * 0.70710678118654752f));
}

__global__ __launch_bounds__(256, 2)
void moe_mma(const float* __restrict__ Asrc, const float* __restrict__ W,
             float* __restrict__ FEO, int Kd, int Nd, int which) {
    int e = blockIdx.z;
    int n = g_cnt[e];
    int t0 = blockIdx.y * MOE_M;
    if (t0 >= n) return;
    int nt = min(MOE_M, n - t0);

    extern __shared__ float sm[];
    float* As = sm;
    float* Bs = sm + 2 * MOE_A_ELEMS;
    int* ps = (int*)(Bs + 2 * MOE_B_ELEMS);
    int* prow = ps + MOE_M;

    int tid = threadIdx.x;
    if (tid < MOE_M) {
        int p = (tid < nt) ? g_bucket[e * NPAIR + t0 + tid] : -1;
        ps[tid] = p;
        int r = (p >= 0) ? p : 0;
        prow[tid] = (which == 1) ? (r >> 1) : r;
    }
    __syncthreads();

    const float* Bw = W + (size_t)e * Cc * Ii + blockIdx.x * 128;

    int lane = tid & 31;
    int warp = tid >> 5;
    int wm = warp >> 1;
    int wn = warp & 1;
    int lr = lane >> 2;
    int lc = lane & 3;

    float acc[8][4];
    #pragma unroll
    for (int ni = 0; ni < 8; ni++)
        #pragma unroll
        for (int r = 0; r < 4; r++) acc[ni][r] = 0.f;

    int nIter = Kd >> 5;

    auto loadTile = [&](int it, int buf) {
        int k0 = it * 32;
        float* Ab = As + buf * MOE_A_ELEMS;
        float* Bb = Bs + buf * MOE_B_ELEMS;
        #pragma unroll
        for (int t = 0; t < 2; t++) {
            int id = tid + t * 256;
            int ar = id >> 3, ac4 = id & 7;
            cp16(smem_u32(Ab + ar * A_LD + ac4 * 4),
                 Asrc + (size_t)prow[ar] * Kd + k0 + ac4 * 4);
        }
        #pragma unroll
        for (int t = 0; t < 4; t++) {
            int id = tid + t * 256;
            int br = id >> 5, bc4 = id & 31;
            cp16(smem_u32(Bb + br * B_LD + bc4 * 4),
                 Bw + (size_t)(k0 + br) * Nd + bc4 * 4);
        }
    };

    loadTile(0, 0);
    asm volatile("cp.async.commit_group;");

    for (int it = 0; it < nIter; it++) {
        int buf = it & 1;
        if (it + 1 < nIter) {
            loadTile(it + 1, buf ^ 1);
            asm volatile("cp.async.commit_group;");
            asm volatile("cp.async.wait_group 1;");
        } else {
            asm volatile("cp.async.wait_group 0;");
        }
        __syncthreads();

        const float* Ab = As + buf * MOE_A_ELEMS;
        const float* Bb = Bs + buf * MOE_B_ELEMS;
        #pragma unroll
        for (int ks = 0; ks < 4; ks++) {
            int kk = ks * 8;
            const float* ap = Ab + (wm * 16 + lr) * A_LD + kk + lc;
            uint32_t ah[4];
            ah[0] = f2tf(ap[0]);
            ah[1] = f2tf(ap[8 * A_LD]);
            ah[2] = f2tf(ap[4]);
            ah[3] = f2tf(ap[8 * A_LD + 4]);
            #pragma unroll
            for (int ni = 0; ni < 8; ni++) {
                const float* bp = Bb + (kk + lc) * B_LD + wn * 64 + ni * 8 + lr;
                uint32_t bh[2];
                bh[0] = f2tf(bp[0]);
                bh[1] = f2tf(bp[4 * B_LD]);
                mma_tf32(acc[ni], ah, bh);
            }
        }
        __syncthreads();
    }

    int colBase = blockIdx.x * 128 + wn * 64;
    int tr0 = wm * 16 + lr;
    #pragma unroll
    for (int ni = 0; ni < 8; ni++) {
        int gc = colBase + ni * 8 + 2 * lc;
        if (tr0 < nt) {
            int p = ps[tr0];
            if (which == 1) {
                float* o = g_hid + (size_t)p * Ii + gc;
                o[0] = gelu_f(acc[ni][0]); o[1] = gelu_f(acc[ni][1]);
            } else {
                float* o = g_po + (size_t)p * Cc + gc;
                o[0] = acc[ni][0]; o[1] = acc[ni][1];
                if (FEO) {
                    float* f = FEO + ((size_t)(p >> 1) * Ee + e) * Cc + gc;
                    f[0] = acc[ni][0]; f[1] = acc[ni][1];
                }
            }
        }
        if (tr0 + 8 < nt) {
            int p = ps[tr0 + 8];
            if (which == 1) {
                float* o = g_hid + (size_t)p * Ii + gc;
                o[0] = gelu_f(acc[ni][2]); o[1] = gelu_f(acc[ni][3]);
            } else {
                float* o = g_po + (size_t)p * Cc + gc;
                o[0] = acc[ni][2]; o[1] = acc[ni][3];
                if (FEO) {
                    float* f = FEO + ((size_t)(p >> 1) * Ee + e) * Cc + gc;
                    f[0] = acc[ni][2]; f[1] = acc[ni][3];
                }
            }
        }
    }
}

// ---------------- flash-style tensor-core attention (2 CTAs/SM) ----------------
#define FA_LD 68
#define FA_SMEM (4 * 64 * FA_LD * 4)

__global__ __launch_bounds__(128, 2)
void fattn_kernel(const float* __restrict__ Q, const float* __restrict__ Km,
                  const float* __restrict__ Vm, float* __restrict__ AO) {
    extern __shared__ float fs[];
    float* Qs = fs;
    float* Ks = fs + 64 * FA_LD;
    float* Vs = fs + 2 * 64 * FA_LD;
    float* Ps = fs + 3 * 64 * FA_LD;

    int qt = blockIdx.x;
    int bh = blockIdx.y;
    int bb = bh >> 3, hh = bh & 7;
    int q0 = qt * 64;

    int tid = threadIdx.x;
    int lane = tid & 31;
    int warp = tid >> 5;
    int lr = lane >> 2;
    int lc = lane & 3;
    int rbase = warp * 16;

    #pragma unroll
    for (int t = 0; t < 8; t++) {
        int id = tid + t * 128;
        int r = id >> 4, c4 = id & 15;
        cp16(smem_u32(Qs + r * FA_LD + c4 * 4),
             Q + (size_t)(bb * Tt + q0 + r) * Cc + hh * Dd + c4 * 4);
    }
    asm volatile("cp.async.commit_group;");

    float m_a = -1e30f, m_b = -1e30f, l_a = 0.f, l_b = 0.f;
    float o[8][4];
    #pragma unroll
    for (int ni = 0; ni < 8; ni++)
        #pragma unroll
        for (int r = 0; r < 4; r++) o[ni][r] = 0.f;

    for (int jt = 0; jt <= qt; jt++) {
        int j0 = jt * 64;
        #pragma unroll
        for (int t = 0; t < 8; t++) {
            int id = tid + t * 128;
            int r = id >> 4, c4 = id & 15;
            cp16(smem_u32(Ks + r * FA_LD + c4 * 4),
                 Km + (size_t)(bb * Tt + j0 + r) * Cc + hh * Dd + c4 * 4);
        }
        asm volatile("cp.async.commit_group;");
        #pragma unroll
        for (int t = 0; t < 8; t++) {
            int id = tid + t * 128;
            int r = id >> 4, c4 = id & 15;
            float4 v = *reinterpret_cast<const float4*>(
                Vm + (size_t)(bb * Tt + j0 + r) * Cc + hh * Dd + c4 * 4);
            Vs[(c4 * 4 + 0) * FA_LD + r] = v.x;
            Vs[(c4 * 4 + 1) * FA_LD + r] = v.y;
            Vs[(c4 * 4 + 2) * FA_LD + r] = v.z;
            Vs[(c4 * 4 + 3) * FA_LD + r] = v.w;
        }
        asm volatile("cp.async.wait_group 0;");
        __syncthreads();

        float s[8][4];
        #pragma unroll
        for (int ni = 0; ni < 8; ni++)
            #pragma unroll
            for (int r = 0; r < 4; r++) s[ni][r] = 0.f;

        #pragma unroll
        for (int ks = 0; ks < 8; ks++) {
            int kk = ks * 8;
            const float* ap = Qs + (rbase + lr) * FA_LD + kk + lc;
            uint32_t ah[4], al[4];
            f2tf2(ap[0],              ah[0], al[0]);
            f2tf2(ap[8 * FA_LD],      ah[1], al[1]);
            f2tf2(ap[4],              ah[2], al[2]);
            f2tf2(ap[8 * FA_LD + 4],  ah[3], al[3]);
            #pragma unroll
            for (int ni = 0; ni < 8; ni++) {
                const float* bp = Ks + (ni * 8 + lr) * FA_LD + kk + lc;
                uint32_t bhh[2], bll[2];
                f2tf2(bp[0], bhh[0], bll[0]);
                f2tf2(bp[4], bhh[1], bll[1]);
                mma_tf32(s[ni], ah, bhh);
                mma_tf32(s[ni], al, bhh);
                mma_tf32(s[ni], ah, bll);
            }
        }

        int qga = q0 + rbase + lr;
        int qgb = qga + 8;
        #pragma unroll
        for (int ni = 0; ni < 8; ni++) {
            int c0 = j0 + ni * 8 + 2 * lc;
            int c1 = c0 + 1;
            s[ni][0] = (c0 <= qga) ? s[ni][0] * 0.125f : -1e30f;
            s[ni][1] = (c1 <= qga) ? s[ni][1] * 0.125f : -1e30f;
            s[ni][2] = (c0 <= qgb) ? s[ni][2] * 0.125f : -1e30f;
            s[ni][3] = (c1 <= qgb) ? s[ni][3] * 0.125f : -1e30f;
        }

        float mxa = -1e30f, mxb = -1e30f;
        #pragma unroll
        for (int ni = 0; ni < 8; ni++) {
            mxa = fmaxf(mxa, fmaxf(s[ni][0], s[ni][1]));
            mxb = fmaxf(mxb, fmaxf(s[ni][2], s[ni][3]));
        }
        mxa = fmaxf(mxa, __shfl_xor_sync(0xffffffff, mxa, 1));
        mxa = fmaxf(mxa, __shfl_xor_sync(0xffffffff, mxa, 2));
        mxb = fmaxf(mxb, __shfl_xor_sync(0xffffffff, mxb, 1));
        mxb = fmaxf(mxb, __shfl_xor_sync(0xffffffff, mxb, 2));

        float mna = fmaxf(m_a, mxa);
        float mnb = fmaxf(m_b, mxb);
        float sca = __expf(m_a - mna);
        float scb = __expf(m_b - mnb);

        float sa = 0.f, sb = 0.f;
        #pragma unroll
        for (int ni = 0; ni < 8; ni++) {
            float p0 = __expf(s[ni][0] - mna);
            float p1 = __expf(s[ni][1] - mna);
            float p2 = __expf(s[ni][2] - mnb);
            float p3 = __expf(s[ni][3] - mnb);
            sa += p0 + p1; sb += p2 + p3;
            int cc0 = ni * 8 + 2 * lc;
            Ps[(rbase + lr) * FA_LD + cc0]     = p0;
            Ps[(rbase + lr) * FA_LD + cc0 + 1] = p1;
            Ps[(rbase + lr + 8) * FA_LD + cc0]     = p2;
            Ps[(rbase + lr + 8) * FA_LD + cc0 + 1] = p3;
        }
        sa += __shfl_xor_sync(0xffffffff, sa, 1);
        sa += __shfl_xor_sync(0xffffffff, sa, 2);
        sb += __shfl_xor_sync(0xffffffff, sb, 1);
        sb += __shfl_xor_sync(0xffffffff, sb, 2);

        l_a = l_a * sca + sa;
        l_b = l_b * scb + sb;
        m_a = mna; m_b = mnb;

        #pragma unroll
        for (int ni = 0; ni < 8; ni++) {
            o[ni][0] *= sca; o[ni][1] *= sca;
            o[ni][2] *= scb; o[ni][3] *= scb;
        }
        __syncwarp();

        #pragma unroll
        for (int ks = 0; ks < 8; ks++) {
            int kk = ks * 8;
            const float* ap = Ps + (rbase + lr) * FA_LD + kk + lc;
            uint32_t ah[4], al[4];
            f2tf2(ap[0],              ah[0], al[0]);
            f2tf2(ap[8 * FA_LD],      ah[1], al[1]);
            f2tf2(ap[4],              ah[2], al[2]);
            f2tf2(ap[8 * FA_LD + 4],  ah[3], al[3]);
            #pragma unroll
            for (int ni = 0; ni < 8; ni++) {
                const float* bp = Vs + (ni * 8 + lr) * FA_LD + kk + lc;
                uint32_t bhh[2], bll[2];
                f2tf2(bp[0], bhh[0], bll[0]);
                f2tf2(bp[4], bhh[1], bll[1]);
                mma_tf32(o[ni], ah, bhh);
                mma_tf32(o[ni], al, bhh);
                mma_tf32(o[ni], ah, bll);
            }
        }
        __syncthreads();
    }

    float ia = 1.f / l_a;
    float ib = 1.f / l_b;
    int qra = bb * Tt + q0 + rbase + lr;
    #pragma unroll
    for (int ni = 0; ni < 8; ni++) {
        int gc = hh * Dd + ni * 8 + 2 * lc;
        *reinterpret_cast<float2*>(AO + (size_t)qra * Cc + gc) =
            make_float2(o[ni][0] * ia, o[ni][1] * ia);
        *reinterpret_cast<float2*>(AO + (size_t)(qra + 8) * Cc + gc) =
            make_float2(o[ni][2] * ib, o[ni][3] * ib);
    }
}

// ---------------- combine + h tf32 round (fused) ----------------
__global__ void moe_combine_round(float* __restrict__ HT) {
    int t = blockIdx.x;
    float w0 = g_rw[t * 2], w1r = g_rw[t * 2 + 1];
    float* hrow = g_h + (size_t)t * Cc;
    const float* p0 = g_po + (size_t)(t * 2) * Cc;
    const float* p1 = g_po + (size_t)(t * 2 + 1) * Cc;
    for (int c = threadIdx.x; c < Cc; c += 128) {
        float nv = hrow[c] + w0 * p0[c] + w1r * p1[c];
        hrow[c] = nv;
        HT[(size_t)t * Cc + c] = __uint_as_float(f2tf(nv));
    }
}

// ---------------- launch ----------------
extern "C" void kernel_launch(void* const* d_in, const int* in_sizes, int n_in,
                              void* d_out, int out_size) {
    const int*   ids  = (const int*)d_in[0];
    const float* emb  = (const float*)d_in[1];
    const float* wq   = (const float*)d_in[2];
    const float* wk   = (const float*)d_in[3];
    const float* wv   = (const float*)d_in[4];
    const float* wo   = (const float*)d_in[5];
    const float* gate = (const float*)d_in[6];
    const float* w1   = (const float*)d_in[7];
    const float* w2   = (const float*)d_in[8];
    const float* g1   = (const float*)d_in[9];
    const float* b1   = (const float*)d_in[10];
    const float* g2   = (const float*)d_in[11];
    const float* b2   = (const float*)d_in[12];
    const float* lm   = (const float*)d_in[13];
    float* out = (float*)d_out;

    float *p_h, *p_x, *p_q, *p_k, *p_v, *p_ao, *p_x2, *p_rl, *p_hid, *p_ht;
    cudaGetSymbolAddress((void**)&p_h,  g_h);
    cudaGetSymbolAddress((void**)&p_x,  g_x);
    cudaGetSymbolAddress((void**)&p_q,  g_q);
    cudaGetSymbolAddress((void**)&p_k,  g_k);
    cudaGetSymbolAddress((void**)&p_v,  g_v);
    cudaGetSymbolAddress((void**)&p_ao, g_ao);
    cudaGetSymbolAddress((void**)&p_x2, g_x2);
    cudaGetSymbolAddress((void**)&p_rl, g_rl);
    cudaGetSymbolAddress((void**)&p_hid, g_hid);
    cudaGetSymbolAddress((void**)&p_ht, g_ht);

    cudaFuncSetAttribute((const void*)mma_gemm<1,0,1,1>,
                         cudaFuncAttributeMaxDynamicSharedMemorySize, GEMM_SMEM_BYTES);
    cudaFuncSetAttribute((const void*)mma_gemm<0,1,0,1>,
                         cudaFuncAttributeMaxDynamicSharedMemorySize, GEMM_SMEM_BYTES);
    cudaFuncSetAttribute((const void*)moe_mma,
                         cudaFuncAttributeMaxDynamicSharedMemorySize, MOE_SMEM_BYTES);
    cudaFuncSetAttribute((const void*)fattn_kernel,
                         cudaFuncAttributeMaxDynamicSharedMemorySize, FA_SMEM);

    const size_t L_LOG = (size_t)NTOK * Vv;
    const size_t L_FEO = (size_t)NTOK * Ee * Cc;
    const size_t L_RL  = (size_t)NTOK * Ee;
    const size_t L_X2  = (size_t)NTOK * Cc;
    const size_t OFF_FEO = L_LOG;
    const size_t OFF_RL  = OFF_FEO + L_FEO;
    const size_t OFF_X2  = OFF_RL + L_RL;
    bool full = (size_t)out_size >= OFF_X2 + L_X2;

    // fused embedding + LN1 (+ counter zeroing)
    embed_ln_kernel<<<NTOK, 128>>>(ids, emb, g1, b1, p_h, p_x);

    // fused QKV (2-stage, proven)
    mma_gemm<1,0,1,1><<<dim3(Cc / 128, NTOK / 128, 3), 256, GEMM_SMEM_BYTES>>>(
        p_x, wq, wk, wv, nullptr, p_q, p_k, p_v, NTOK, Cc, Cc);

    fattn_kernel<<<dim3(Tt / 64, Bsz * Hh), 128, FA_SMEM>>>(p_q, p_k, p_v, p_ao);

    mma_gemm<1,0,1,1><<<dim3(Cc / 128, NTOK / 128, 1), 256, GEMM_SMEM_BYTES>>>(
        p_ao, wo, wo, wo, p_h, p_h, p_h, p_h, NTOK, Cc, Cc);

    // fused LN2 + router + top-2 + bucketing
    ln2_router_kernel<<<NTOK, 128>>>(p_h, g2, b2, gate, p_x2, p_rl);

    if (full) cudaMemsetAsync(out + OFF_FEO, 0, L_FEO * sizeof(float));

    moe_mma<<<dim3(Ii / 128, MOE_YTILES, Ee), 256, MOE_SMEM_BYTES>>>(
        p_x2, w1, nullptr, Cc, Ii, 1);
    moe_mma<<<dim3(Cc / 128, MOE_YTILES, Ee), 256, MOE_SMEM_BYTES>>>(
        p_hid, w2, full ? (out + OFF_FEO) : nullptr, Ii, Cc, 2);

    moe_combine_round<<<NTOK, 128>>>(p_ht);

    // lm_head: proven 2-stage, A pre-rounded, B in-loop CVT
    mma_gemm<0,1,0,1><<<dim3(NTOK / 128, Vv / 128, 1), 256, GEMM_SMEM_BYTES>>>(
        p_ht, lm, lm, lm, nullptr, out, out, out, NTOK, Vv, Cc);

    if (full) {
        cudaMemcpyAsync(out + OFF_RL, p_rl, L_RL * sizeof(float), cudaMemcpyDeviceToDevice);
        cudaMemcpyAsync(out + OFF_X2, p_x2, L_X2 * sizeof(float), cudaMemcpyDeviceToDevice);
    }
}